// round 4
// baseline (speedup 1.0000x reference)
#include <cuda_runtime.h>
#include <cstdint>
#include <cstddef>

// Problem constants
#define B_   2
#define S_   2048
#define D_   1024
#define H_   16
#define DEP_ 64

// Scratch: head-split projections + attention output (64 MB total).
// (sanctioned scratch mechanism: __device__ globals, no allocations)
__device__ float g_qh[B_ * H_ * S_ * DEP_];
__device__ float g_kh[B_ * H_ * S_ * DEP_];
__device__ float g_vh[B_ * H_ * S_ * DEP_];
__device__ float g_attn[B_ * H_ * S_ * DEP_];

// ---------------------------------------------------------------------------
// Generic double-buffered SGEMM, C = A * B^T (+bias)(*scale), fp32.
//
// MODE 0: projection   y = X @ W^T + b   (M=4096,N=1024,K=1024), output
//         written head-split into [B,H,S,DEP] layout, scaled after bias.
// MODE 1: scores       L[z] = qh[z] @ kh[z]^T   (per z=b*H+h: M=N=2048,K=64)
// MODE 2: out proj     out = attn_gathered @ Wo^T + bo (M=4096,N=1024,K=1024)
//         A is gathered from [B,H,S,DEP] layout.
// MODE 3: PV           attn[z] = W[z] @ vh[z]   (M=2048,N=64,K=2048), B is NN
//
// BM=128, BK=16, BN=128 (64 for MODE 3), 256 threads, 8x8 (8x4) microtile.
// ---------------------------------------------------------------------------
template <int MODE>
__global__ __launch_bounds__(256, 2) void gemm_k(const float* __restrict__ A,
                                                 const float* __restrict__ Bm,
                                                 const float* __restrict__ bias,
                                                 float* __restrict__ C,
                                                 float scale) {
    constexpr int BM   = 128;
    constexpr int BK   = 16;
    constexpr int BN   = (MODE == 3) ? 64 : 128;
    constexpr int TN   = (MODE == 3) ? 4 : 8;
    constexpr int KDIM = (MODE == 1) ? 64 : ((MODE == 3) ? 2048 : 1024);
    constexpr int NT   = KDIM / BK;

    __shared__ __align__(16) float As[2][BK][BM + 4];
    __shared__ __align__(16) float Bs[2][BK][BN + 4];

    const int tid = threadIdx.x;
    const int tx  = tid & 15;   // 0..15 -> N direction
    const int ty  = tid >> 4;   // 0..15 -> M direction
    const int m0  = blockIdx.y * BM;
    const int n0  = blockIdx.x * BN;
    const int z   = blockIdx.z;

    float acc[8][TN];
#pragma unroll
    for (int i = 0; i < 8; ++i)
#pragma unroll
        for (int j = 0; j < TN; ++j) acc[i][j] = 0.0f;

    float4 ra[2];
    float4 rb[2];

    // Global A address for logical A[m, k] (k-contiguous, 16B aligned).
    auto a_ptr = [&](int m, int k) -> const float4* {
        if constexpr (MODE == 0) {
            return (const float4*)(A + (size_t)m * 1024 + k);
        } else if constexpr (MODE == 1) {
            return (const float4*)(A + ((size_t)z * S_ + m) * DEP_ + k);
        } else if constexpr (MODE == 2) {
            const int h = k >> 6, d = k & 63;
            const int b = m >> 11, s = m & 2047;
            return (const float4*)(A + (((size_t)b * H_ + h) * S_ + s) * DEP_ + d);
        } else {  // MODE 3: A = weights, row-major [S_, S_] per z
            return (const float4*)(A + ((size_t)z * S_ + m) * S_ + k);
        }
    };
    // Global B address for logical B[n, k] (NT modes only).
    auto b_ptr = [&](int n, int k) -> const float4* {
        if constexpr (MODE == 1) {
            return (const float4*)(Bm + ((size_t)z * S_ + n) * DEP_ + k);
        } else {
            return (const float4*)(Bm + (size_t)n * 1024 + k);
        }
    };

    auto fetch = [&](int k0) {
#pragma unroll
        for (int it = 0; it < 2; ++it) {
            const int f4 = tid + it * 256;
            const int r  = f4 >> 2;
            const int kk = (f4 & 3) * 4;
            ra[it] = *a_ptr(m0 + r, k0 + kk);
        }
        if constexpr (MODE == 3) {
            const int r = tid >> 4;           // k-row within tile (16 rows)
            const int n = (tid & 15) * 4;     // 64 cols / 4
            rb[0] = *(const float4*)(Bm + ((size_t)z * S_ + k0 + r) * DEP_ + n0 + n);
        } else {
#pragma unroll
            for (int it = 0; it < 2; ++it) {
                const int f4 = tid + it * 256;
                const int r  = f4 >> 2;
                const int kk = (f4 & 3) * 4;
                rb[it] = *b_ptr(n0 + r, k0 + kk);
            }
        }
    };

    auto stage = [&](int buf) {
#pragma unroll
        for (int it = 0; it < 2; ++it) {
            const int f4 = tid + it * 256;
            const int r  = f4 >> 2;
            const int kk = (f4 & 3) * 4;
            As[buf][kk + 0][r] = ra[it].x;
            As[buf][kk + 1][r] = ra[it].y;
            As[buf][kk + 2][r] = ra[it].z;
            As[buf][kk + 3][r] = ra[it].w;
        }
        if constexpr (MODE == 3) {
            const int r = tid >> 4;
            const int n = (tid & 15) * 4;
            *(float4*)&Bs[buf][r][n] = rb[0];
        } else {
#pragma unroll
            for (int it = 0; it < 2; ++it) {
                const int f4 = tid + it * 256;
                const int r  = f4 >> 2;
                const int kk = (f4 & 3) * 4;
                Bs[buf][kk + 0][r] = rb[it].x;
                Bs[buf][kk + 1][r] = rb[it].y;
                Bs[buf][kk + 2][r] = rb[it].z;
                Bs[buf][kk + 3][r] = rb[it].w;
            }
        }
    };

    auto compute = [&](int buf) {
#pragma unroll
        for (int kk = 0; kk < BK; ++kk) {
            float av[8];
            const float4 a0 = *(const float4*)&As[buf][kk][ty * 8];
            const float4 a1 = *(const float4*)&As[buf][kk][ty * 8 + 4];
            av[0] = a0.x; av[1] = a0.y; av[2] = a0.z; av[3] = a0.w;
            av[4] = a1.x; av[5] = a1.y; av[6] = a1.z; av[7] = a1.w;
            float bv[TN];
            if constexpr (TN == 8) {
                const float4 b0 = *(const float4*)&Bs[buf][kk][tx * 8];
                const float4 b1 = *(const float4*)&Bs[buf][kk][tx * 8 + 4];
                bv[0] = b0.x; bv[1] = b0.y; bv[2] = b0.z; bv[3] = b0.w;
                bv[4] = b1.x; bv[5] = b1.y; bv[6] = b1.z; bv[7] = b1.w;
            } else {
                const float4 b0 = *(const float4*)&Bs[buf][kk][tx * 4];
                bv[0] = b0.x; bv[1] = b0.y; bv[2] = b0.z; bv[3] = b0.w;
            }
#pragma unroll
            for (int i = 0; i < 8; ++i)
#pragma unroll
                for (int j = 0; j < TN; ++j) acc[i][j] += av[i] * bv[j];
        }
    };

    fetch(0);
    stage(0);
    __syncthreads();
#pragma unroll 1
    for (int t = 0; t < NT; ++t) {
        if (t + 1 < NT) fetch((t + 1) * BK);
        compute(t & 1);
        if (t + 1 < NT) stage((t + 1) & 1);
        __syncthreads();
    }

    // Epilogue
    float bf[TN];
    if constexpr (MODE == 0 || MODE == 2) {
#pragma unroll
        for (int j = 0; j < TN; ++j) bf[j] = bias[n0 + tx * TN + j];
    }

#pragma unroll
    for (int i = 0; i < 8; ++i) {
        const int m = m0 + ty * 8 + i;
        if constexpr (MODE == 0) {
            const int n = n0 + tx * 8;
            const int b = m >> 11, s = m & 2047;
            const int h = n >> 6, d = n & 63;
            float* dst = C + (((size_t)b * H_ + h) * S_ + s) * DEP_ + d;
            float4 o0, o1;
            o0.x = (acc[i][0] + bf[0]) * scale;
            o0.y = (acc[i][1] + bf[1]) * scale;
            o0.z = (acc[i][2] + bf[2]) * scale;
            o0.w = (acc[i][3] + bf[3]) * scale;
            o1.x = (acc[i][4] + bf[4]) * scale;
            o1.y = (acc[i][5] + bf[5]) * scale;
            o1.z = (acc[i][6] + bf[6]) * scale;
            o1.w = (acc[i][7] + bf[7]) * scale;
            *(float4*)dst       = o0;
            *(float4*)(dst + 4) = o1;
        } else if constexpr (MODE == 1) {
            float* dst = C + ((size_t)z * S_ + m) * S_ + n0 + tx * 8;
            float4 o0 = {acc[i][0], acc[i][1], acc[i][2], acc[i][3]};
            float4 o1 = {acc[i][4], acc[i][5], acc[i][6], acc[i][7]};
            *(float4*)dst       = o0;
            *(float4*)(dst + 4) = o1;
        } else if constexpr (MODE == 2) {
            float* dst = C + (size_t)m * 1024 + n0 + tx * 8;
            float4 o0 = {acc[i][0] + bf[0], acc[i][1] + bf[1],
                         acc[i][2] + bf[2], acc[i][3] + bf[3]};
            float4 o1 = {acc[i][4] + bf[4], acc[i][5] + bf[5],
                         acc[i][6] + bf[6], acc[i][7] + bf[7]};
            *(float4*)dst       = o0;
            *(float4*)(dst + 4) = o1;
        } else {  // MODE 3
            float* dst = C + ((size_t)z * S_ + m) * DEP_ + n0 + tx * 4;
            float4 o0 = {acc[i][0], acc[i][1], acc[i][2], acc[i][3]};
            *(float4*)dst = o0;
        }
    }
}

// ---------------------------------------------------------------------------
// In-place row softmax on [rows, 2048], one block per row, values register-
// resident (single read + single write of the 536 MB weights region).
// ---------------------------------------------------------------------------
__global__ __launch_bounds__(256) void softmax_k(float* __restrict__ W) {
    const size_t row = blockIdx.x;
    float* p = W + row * (size_t)S_;
    const int tid = threadIdx.x;
    const int wr  = tid >> 5;
    const int ln  = tid & 31;

    const float4 v0 = *(const float4*)(p + tid * 8);
    const float4 v1 = *(const float4*)(p + tid * 8 + 4);
    float x[8] = {v0.x, v0.y, v0.z, v0.w, v1.x, v1.y, v1.z, v1.w};

    float mx = x[0];
#pragma unroll
    for (int i = 1; i < 8; ++i) mx = fmaxf(mx, x[i]);
#pragma unroll
    for (int o = 16; o > 0; o >>= 1) mx = fmaxf(mx, __shfl_xor_sync(0xFFFFFFFFu, mx, o));

    __shared__ float red_mx[8];
    __shared__ float red_sm[8];
    if (ln == 0) red_mx[wr] = mx;
    __syncthreads();
    mx = red_mx[0];
#pragma unroll
    for (int i = 1; i < 8; ++i) mx = fmaxf(mx, red_mx[i]);

    float e[8];
    float s = 0.0f;
#pragma unroll
    for (int i = 0; i < 8; ++i) {
        e[i] = expf(x[i] - mx);
        s += e[i];
    }
#pragma unroll
    for (int o = 16; o > 0; o >>= 1) s += __shfl_xor_sync(0xFFFFFFFFu, s, o);
    if (ln == 0) red_sm[wr] = s;
    __syncthreads();
    s = red_sm[0];
#pragma unroll
    for (int i = 1; i < 8; ++i) s += red_sm[i];
    const float inv = 1.0f / s;

    float4 o0 = {e[0] * inv, e[1] * inv, e[2] * inv, e[3] * inv};
    float4 o1 = {e[4] * inv, e[5] * inv, e[6] * inv, e[7] * inv};
    *(float4*)(p + tid * 8)     = o0;
    *(float4*)(p + tid * 8 + 4) = o1;
}

// ---------------------------------------------------------------------------
// Launch. Inputs (metadata order): q,k,v,mask,Wq,bq,Wk,bk,Wv,bv,Wo,bo.
// Output: out [B,S,D] followed by weights [B,H,S,S] (tuple flattened).
// mask*1e-9 is numerically irrelevant at fp32 (perturbs O(1) logits by 1e-9,
// below ulp) and is skipped.
// ---------------------------------------------------------------------------
extern "C" void kernel_launch(void* const* d_in, const int* in_sizes, int n_in,
                              void* d_out, int out_size) {
    (void)in_sizes; (void)n_in; (void)out_size;

    const float* q  = (const float*)d_in[0];
    const float* k  = (const float*)d_in[1];
    const float* v  = (const float*)d_in[2];
    const float* Wq = (const float*)d_in[4];
    const float* bq = (const float*)d_in[5];
    const float* Wk = (const float*)d_in[6];
    const float* bk = (const float*)d_in[7];
    const float* Wv = (const float*)d_in[8];
    const float* bv = (const float*)d_in[9];
    const float* Wo = (const float*)d_in[10];
    const float* bo = (const float*)d_in[11];

    float* out = (float*)d_out;
    float* wts = out + (size_t)B_ * S_ * D_;  // weights region (also logits scratch)

    float *qh, *kh, *vh, *attn;
    cudaGetSymbolAddress((void**)&qh, g_qh);
    cudaGetSymbolAddress((void**)&kh, g_kh);
    cudaGetSymbolAddress((void**)&vh, g_vh);
    cudaGetSymbolAddress((void**)&attn, g_attn);

    const dim3 blk(256);
    // QKV projections (head-split layout, 1/sqrt(depth) folded into Q)
    const dim3 gproj(D_ / 128, (B_ * S_) / 128, 1);
    gemm_k<0><<<gproj, blk>>>(q, Wq, bq, qh, 0.125f);
    gemm_k<0><<<gproj, blk>>>(k, Wk, bk, kh, 1.0f);
    gemm_k<0><<<gproj, blk>>>(v, Wv, bv, vh, 1.0f);

    // Logits -> d_out weights region
    const dim3 gsc(S_ / 128, S_ / 128, B_ * H_);
    gemm_k<1><<<gsc, blk>>>(qh, kh, nullptr, wts, 1.0f);

    // In-place softmax
    softmax_k<<<B_ * H_ * S_, blk>>>(wts);

    // attn = weights @ V
    const dim3 gpv(1, S_ / 128, B_ * H_);
    gemm_k<3><<<gpv, blk>>>(wts, vh, nullptr, attn, 1.0f);

    // Output projection
    const dim3 gout(D_ / 128, (B_ * S_) / 128, 1);
    gemm_k<2><<<gout, blk>>>(attn, Wo, bo, out, 1.0f);
}

// round 6
// speedup vs baseline: 1.2337x; 1.2337x over previous
#include <cuda_runtime.h>
#include <cuda_bf16.h>
#include <cstdint>
#include <cstddef>

// Problem constants
#define B_   2
#define S_   2048
#define D_   1024
#define H_   16
#define DEP_ 64

// Scratch (sanctioned: __device__ globals)
__device__ float g_qh[B_ * H_ * S_ * DEP_];
__device__ float g_kh[B_ * H_ * S_ * DEP_];
__device__ float g_vh[B_ * H_ * S_ * DEP_];
__device__ float g_attn[B_ * H_ * S_ * DEP_];

// ---------------------------------------------------------------------------
// bf16x3 split helpers: x = hi + lo with hi,lo bf16; products hi*hi + hi*lo +
// lo*hi recover ~17 mantissa bits (lo*lo dropped, rel err ~4e-6).
// ---------------------------------------------------------------------------
__device__ __forceinline__ uint32_t bfbits(float x) {
    __nv_bfloat16 b = __float2bfloat16(x);  // RN
    return (uint32_t)__bfloat16_as_ushort(b);
}
__device__ __forceinline__ void split2(float x0, float x1, uint32_t& hp, uint32_t& lp) {
    uint32_t h0 = bfbits(x0), h1 = bfbits(x1);
    float r0 = x0 - __uint_as_float(h0 << 16);
    float r1 = x1 - __uint_as_float(h1 << 16);
    hp = h0 | (h1 << 16);              // even-k element in LOW half
    lp = bfbits(r0) | (bfbits(r1) << 16);
}
__device__ __forceinline__ void split1(float x, uint16_t& h, uint16_t& l) {
    uint32_t hb = bfbits(x);
    float r = x - __uint_as_float(hb << 16);
    h = (uint16_t)hb;
    l = (uint16_t)bfbits(r);
}

__device__ __forceinline__ void mma16816(float* c, const uint32_t* a, const uint32_t* b) {
    asm volatile(
        "mma.sync.aligned.m16n8k16.row.col.f32.bf16.bf16.f32 "
        "{%0,%1,%2,%3}, {%4,%5,%6,%7}, {%8,%9}, {%0,%1,%2,%3};"
        : "+f"(c[0]), "+f"(c[1]), "+f"(c[2]), "+f"(c[3])
        : "r"(a[0]), "r"(a[1]), "r"(a[2]), "r"(a[3]), "r"(b[0]), "r"(b[1]));
}

// ---------------------------------------------------------------------------
// Tensor-core GEMM, C = A * B^T (+bias)(*scale), bf16x3 split, fp32 accum.
//
// MODE 0: projection   y = X @ W^T + b   (M=4096,N=1024,K=1024) -> head-split
// MODE 1: scores       L[z] = qh[z] @ kh[z]^T  (per z: M=N=2048, K=64)
// MODE 2: out proj     out = attn_gathered @ Wo^T + bo
// MODE 3: PV           attn[z] = W[z] @ vh[z]  (M=2048,N=64,K=2048), B is NN
//
// BM=128, BN=64, BK=16. 256 threads = 8 warps (4m x 2n), warp tile 32x32.
// Smem holds hi/lo bf16 planes PRE-PACKED in m16n8k16 fragment layout.
// ---------------------------------------------------------------------------
template <int MODE>
__global__ __launch_bounds__(256, 2) void gemm_k(const float* __restrict__ A,
                                                 const float* __restrict__ Bm,
                                                 const float* __restrict__ bias,
                                                 float* __restrict__ C,
                                                 float scale) {
    constexpr int BM   = 128;
    constexpr int BN   = 64;
    constexpr int BK   = 16;
    constexpr int KDIM = (MODE == 1) ? 64 : ((MODE == 3) ? 2048 : 1024);
    constexpr int NST  = KDIM / BK;

    // [buf][plane hi/lo][tile][lane][reg]
    __shared__ __align__(16) uint32_t As[2][2][8][32][4];  // 8 m16-tiles
    __shared__ __align__(16) uint32_t Bs[2][2][8][32][2];  // 8 n8-tiles

    const int tid  = threadIdx.x;
    const int lane = tid & 31;
    const int wid  = tid >> 5;
    const int wm   = wid >> 1;   // 0..3 -> m offset wm*32
    const int wn   = wid & 1;    // 0..1 -> n offset wn*32
    const int g    = lane >> 2;  // fragment group (row/col)
    const int t4   = lane & 3;   // fragment thread-in-group
    const int m0   = blockIdx.y * BM;
    const int n0   = blockIdx.x * BN;
    const int z    = blockIdx.z;

    float acc[2][4][4];
#pragma unroll
    for (int i = 0; i < 2; ++i)
#pragma unroll
        for (int j = 0; j < 4; ++j)
#pragma unroll
            for (int r = 0; r < 4; ++r) acc[i][j][r] = 0.0f;

    float4 ra[2];
    float4 rb;

    // Global A address for logical A[m, k] (k-contiguous, 16B aligned)
    auto a_ptr = [&](int m, int k) -> const float4* {
        if constexpr (MODE == 0) {
            return (const float4*)(A + (size_t)m * 1024 + k);
        } else if constexpr (MODE == 1) {
            return (const float4*)(A + ((size_t)z * S_ + m) * DEP_ + k);
        } else if constexpr (MODE == 2) {
            const int h = k >> 6, d = k & 63;
            const int b = m >> 11, s = m & 2047;
            return (const float4*)(A + (((size_t)b * H_ + h) * S_ + s) * DEP_ + d);
        } else {  // MODE 3: weights, row-major [S_, S_] per z
            return (const float4*)(A + ((size_t)z * S_ + m) * S_ + k);
        }
    };
    // Global B address for logical B[n, k] (NT modes)
    auto b_ptr = [&](int n, int k) -> const float4* {
        if constexpr (MODE == 1) {
            return (const float4*)(Bm + ((size_t)z * S_ + n) * DEP_ + k);
        } else {
            return (const float4*)(Bm + (size_t)n * 1024 + k);
        }
    };

    auto fetch = [&](int k0) {
#pragma unroll
        for (int it = 0; it < 2; ++it) {
            const int f4 = tid + it * 256;
            const int m  = f4 >> 2;
            const int kk = (f4 & 3) * 4;
            ra[it] = *a_ptr(m0 + m, k0 + kk);
        }
        if constexpr (MODE == 3) {
            const int kk = tid >> 4;          // 0..15: k row
            const int d0 = (tid & 15) * 4;    // 0..60: n (depth)
            rb = *(const float4*)(Bm + ((size_t)z * S_ + k0 + kk) * DEP_ + n0 + d0);
        } else {
            const int n  = tid >> 2;          // 0..63
            const int kk = (tid & 3) * 4;
            rb = *b_ptr(n0 + n, k0 + kk);
        }
    };

    auto stage = [&](int buf) {
        // A: thread holds A[m][k0..k0+3] -> two k-pairs -> fragment regs
#pragma unroll
        for (int it = 0; it < 2; ++it) {
            const int f4    = tid + it * 256;
            const int m     = f4 >> 2;
            const int mtile = m >> 4;
            const int rr    = m & 15;
            const int gl    = rr & 7;
            const int rbase = rr >> 3;        // 0: a0/a2 slot, 1: a1/a3 slot
            const int c0    = (f4 & 3) * 2;   // k-pair index 0..7
            uint32_t hp, lp;
            split2(ra[it].x, ra[it].y, hp, lp);
            {
                const int c = c0, t = c & 3, rs = rbase + ((c >= 4) ? 2 : 0);
                As[buf][0][mtile][gl * 4 + t][rs] = hp;
                As[buf][1][mtile][gl * 4 + t][rs] = lp;
            }
            split2(ra[it].z, ra[it].w, hp, lp);
            {
                const int c = c0 + 1, t = c & 3, rs = rbase + ((c >= 4) ? 2 : 0);
                As[buf][0][mtile][gl * 4 + t][rs] = hp;
                As[buf][1][mtile][gl * 4 + t][rs] = lp;
            }
        }
        if constexpr (MODE == 3) {
            // vh is [k, n]: thread holds row kk, cols d0..d0+3 -> scalar halves
            const int kk   = tid >> 4;
            const int d0   = (tid & 15) * 4;
            const int t    = (kk >> 1) & 3;
            const int rs   = kk >> 3;
            const int half = kk & 1;
            const float* vv = (const float*)&rb;
#pragma unroll
            for (int j = 0; j < 4; ++j) {
                const int d = d0 + j;
                const int ntile = d >> 3, gb = d & 7;
                uint16_t h, l;
                split1(vv[j], h, l);
                ((uint16_t*)&Bs[buf][0][ntile][gb * 4 + t][rs])[half] = h;
                ((uint16_t*)&Bs[buf][1][ntile][gb * 4 + t][rs])[half] = l;
            }
        } else {
            // B[n][k0..k0+3] -> two k-pairs -> fragment regs (col-major frag)
            const int n     = tid >> 2;
            const int ntile = n >> 3, gb = n & 7;
            const int c0    = (tid & 3) * 2;
            uint32_t hp, lp;
            split2(rb.x, rb.y, hp, lp);
            {
                const int c = c0;
                Bs[buf][0][ntile][gb * 4 + (c & 3)][c >> 2] = hp;
                Bs[buf][1][ntile][gb * 4 + (c & 3)][c >> 2] = lp;
            }
            split2(rb.z, rb.w, hp, lp);
            {
                const int c = c0 + 1;
                Bs[buf][0][ntile][gb * 4 + (c & 3)][c >> 2] = hp;
                Bs[buf][1][ntile][gb * 4 + (c & 3)][c >> 2] = lp;
            }
        }
    };

    auto compute = [&](int buf) {
        uint32_t bh[4][2], bl[4][2];
#pragma unroll
        for (int nt = 0; nt < 4; ++nt) {
            *(uint2*)bh[nt] = *(const uint2*)&Bs[buf][0][wn * 4 + nt][lane][0];
            *(uint2*)bl[nt] = *(const uint2*)&Bs[buf][1][wn * 4 + nt][lane][0];
        }
#pragma unroll
        for (int mt = 0; mt < 2; ++mt) {
            uint32_t ah[4], al[4];
            *(uint4*)ah = *(const uint4*)&As[buf][0][wm * 2 + mt][lane][0];
            *(uint4*)al = *(const uint4*)&As[buf][1][wm * 2 + mt][lane][0];
#pragma unroll
            for (int nt = 0; nt < 4; ++nt) {
                mma16816(acc[mt][nt], ah, bh[nt]);  // hi*hi
                mma16816(acc[mt][nt], ah, bl[nt]);  // hi*lo
                mma16816(acc[mt][nt], al, bh[nt]);  // lo*hi
            }
        }
    };

    fetch(0);
    stage(0);
    __syncthreads();
#pragma unroll 1
    for (int t = 0; t < NST; ++t) {
        if (t + 1 < NST) fetch((t + 1) * BK);
        compute(t & 1);
        if (t + 1 < NST) stage((t + 1) & 1);
        __syncthreads();
    }

    // Epilogue: c0=(g,2t), c1=(g,2t+1), c2=(g+8,2t), c3=(g+8,2t+1)
#pragma unroll
    for (int mt = 0; mt < 2; ++mt) {
#pragma unroll
        for (int nt = 0; nt < 4; ++nt) {
            const int col = n0 + wn * 32 + nt * 8 + t4 * 2;
            float b0 = 0.0f, b1 = 0.0f;
            if constexpr (MODE == 0 || MODE == 2) {
                b0 = bias[col];
                b1 = bias[col + 1];
            }
#pragma unroll
            for (int rs = 0; rs < 2; ++rs) {
                const int row = m0 + wm * 32 + mt * 16 + g + rs * 8;
                float v0 = acc[mt][nt][rs * 2 + 0];
                float v1 = acc[mt][nt][rs * 2 + 1];
                if constexpr (MODE == 0) {
                    v0 = (v0 + b0) * scale;
                    v1 = (v1 + b1) * scale;
                    const int b = row >> 11, s = row & 2047;
                    const int h = col >> 6, d = col & 63;
                    *(float2*)(C + (((size_t)b * H_ + h) * S_ + s) * DEP_ + d) =
                        make_float2(v0, v1);
                } else if constexpr (MODE == 1) {
                    *(float2*)(C + ((size_t)z * S_ + row) * S_ + col) =
                        make_float2(v0, v1);
                } else if constexpr (MODE == 2) {
                    *(float2*)(C + (size_t)row * D_ + col) =
                        make_float2(v0 + b0, v1 + b1);
                } else {
                    *(float2*)(C + ((size_t)z * S_ + row) * DEP_ + col) =
                        make_float2(v0, v1);
                }
            }
        }
    }
}

// ---------------------------------------------------------------------------
// In-place row softmax on [rows, 2048], one block/row, register-resident.
// ---------------------------------------------------------------------------
__global__ __launch_bounds__(256) void softmax_k(float* __restrict__ W) {
    const size_t row = blockIdx.x;
    float* p = W + row * (size_t)S_;
    const int tid = threadIdx.x;
    const int wr  = tid >> 5;
    const int ln  = tid & 31;

    const float4 v0 = *(const float4*)(p + tid * 8);
    const float4 v1 = *(const float4*)(p + tid * 8 + 4);
    float x[8] = {v0.x, v0.y, v0.z, v0.w, v1.x, v1.y, v1.z, v1.w};

    float mx = x[0];
#pragma unroll
    for (int i = 1; i < 8; ++i) mx = fmaxf(mx, x[i]);
#pragma unroll
    for (int o = 16; o > 0; o >>= 1) mx = fmaxf(mx, __shfl_xor_sync(0xFFFFFFFFu, mx, o));

    __shared__ float red_mx[8];
    __shared__ float red_sm[8];
    if (ln == 0) red_mx[wr] = mx;
    __syncthreads();
    mx = red_mx[0];
#pragma unroll
    for (int i = 1; i < 8; ++i) mx = fmaxf(mx, red_mx[i]);

    float e[8];
    float s = 0.0f;
#pragma unroll
    for (int i = 0; i < 8; ++i) {
        e[i] = expf(x[i] - mx);
        s += e[i];
    }
#pragma unroll
    for (int o = 16; o > 0; o >>= 1) s += __shfl_xor_sync(0xFFFFFFFFu, s, o);
    if (ln == 0) red_sm[wr] = s;
    __syncthreads();
    s = red_sm[0];
#pragma unroll
    for (int i = 1; i < 8; ++i) s += red_sm[i];
    const float inv = 1.0f / s;

    float4 o0 = {e[0] * inv, e[1] * inv, e[2] * inv, e[3] * inv};
    float4 o1 = {e[4] * inv, e[5] * inv, e[6] * inv, e[7] * inv};
    *(float4*)(p + tid * 8)     = o0;
    *(float4*)(p + tid * 8 + 4) = o1;
}

// ---------------------------------------------------------------------------
// Launch. Inputs: q,k,v,mask,Wq,bq,Wk,bk,Wv,bv,Wo,bo.
// Output: out [B,S,D] then weights [B,H,S,S]. mask*1e-9 is below fp32 ulp of
// O(1) logits -> skipped.
// ---------------------------------------------------------------------------
extern "C" void kernel_launch(void* const* d_in, const int* in_sizes, int n_in,
                              void* d_out, int out_size) {
    (void)in_sizes; (void)n_in; (void)out_size;

    const float* q  = (const float*)d_in[0];
    const float* k  = (const float*)d_in[1];
    const float* v  = (const float*)d_in[2];
    const float* Wq = (const float*)d_in[4];
    const float* bq = (const float*)d_in[5];
    const float* Wk = (const float*)d_in[6];
    const float* bk = (const float*)d_in[7];
    const float* Wv = (const float*)d_in[8];
    const float* bv = (const float*)d_in[9];
    const float* Wo = (const float*)d_in[10];
    const float* bo = (const float*)d_in[11];

    float* out = (float*)d_out;
    float* wts = out + (size_t)B_ * S_ * D_;  // weights region (logits scratch)

    float *qh, *kh, *vh, *attn;
    cudaGetSymbolAddress((void**)&qh, g_qh);
    cudaGetSymbolAddress((void**)&kh, g_kh);
    cudaGetSymbolAddress((void**)&vh, g_vh);
    cudaGetSymbolAddress((void**)&attn, g_attn);

    const dim3 blk(256);
    // QKV projections (head-split output, 1/sqrt(depth) folded into Q)
    const dim3 gproj(D_ / 64, (B_ * S_) / 128, 1);
    gemm_k<0><<<gproj, blk>>>(q, Wq, bq, qh, 0.125f);
    gemm_k<0><<<gproj, blk>>>(k, Wk, bk, kh, 1.0f);
    gemm_k<0><<<gproj, blk>>>(v, Wv, bv, vh, 1.0f);

    // Logits -> d_out weights region
    const dim3 gsc(S_ / 64, S_ / 128, B_ * H_);
    gemm_k<1><<<gsc, blk>>>(qh, kh, nullptr, wts, 1.0f);

    // In-place softmax
    softmax_k<<<B_ * H_ * S_, blk>>>(wts);

    // attn = weights @ V
    const dim3 gpv(1, S_ / 128, B_ * H_);
    gemm_k<3><<<gpv, blk>>>(wts, vh, nullptr, attn, 1.0f);

    // Output projection
    const dim3 gout(D_ / 64, (B_ * S_) / 128, 1);
    gemm_k<2><<<gout, blk>>>(attn, Wo, bo, out, 1.0f);
}

// round 7
// speedup vs baseline: 1.8129x; 1.4694x over previous
#include <cuda_runtime.h>
#include <cuda_bf16.h>
#include <cstdint>
#include <cstddef>

// Problem constants
#define B_   2
#define S_   2048
#define D_   1024
#define H_   16
#define DEP_ 64

// ---------------------------------------------------------------------------
// Fragment-layout scratch planes (uint32 units). All operands that we produce
// are stored pre-split (bf16 hi/lo) in the exact m16n8k16 fragment order, so
// GEMM staging is a pure LDG.128 -> STS.128 copy.
// ---------------------------------------------------------------------------
#define PLANE 2097152u   // 2M uint32 = 8 MB
#define WPL   524288u
__device__ uint32_t g_xA[3 * 2 * PLANE];  // split q,k,v   (A-frag, M=4096,K=1024)
__device__ uint32_t g_WB[4 * 2 * WPL];    // split Wq..Wo  (B-frag, N=1024,K=1024)
__device__ uint32_t g_qA[2 * PLANE];      // qh  (A-frag per z, M=2048,K=64)
__device__ uint32_t g_kB[2 * PLANE];      // kh  (B-frag per z, N=2048,K=64)
__device__ uint32_t g_vB[2 * PLANE];      // vh  (B-frag per z, N=64,K=2048)
__device__ uint32_t g_aA[2 * PLANE];      // attn (A-frag, M=4096,K=1024)

// ---------------------------------------------------------------------------
// bf16x3 split helpers (hi*hi + hi*lo + lo*hi; lo*lo dropped, ~17-bit inputs)
// ---------------------------------------------------------------------------
__device__ __forceinline__ uint32_t bfbits(float x) {
    return (uint32_t)__bfloat16_as_ushort(__float2bfloat16(x));
}
__device__ __forceinline__ void split2(float x0, float x1, uint32_t& hp, uint32_t& lp) {
    uint32_t h0 = bfbits(x0), h1 = bfbits(x1);
    float r0 = x0 - __uint_as_float(h0 << 16);
    float r1 = x1 - __uint_as_float(h1 << 16);
    hp = h0 | (h1 << 16);   // even-k element in LOW half
    lp = bfbits(r0) | (bfbits(r1) << 16);
}
__device__ __forceinline__ void split1(float x, uint16_t& h, uint16_t& l) {
    uint32_t hb = bfbits(x);
    float r = x - __uint_as_float(hb << 16);
    h = (uint16_t)hb;
    l = (uint16_t)bfbits(r);
}

__device__ __forceinline__ void mma16816(float* c, const uint32_t* a, const uint32_t* b) {
    asm volatile(
        "mma.sync.aligned.m16n8k16.row.col.f32.bf16.bf16.f32 "
        "{%0,%1,%2,%3}, {%4,%5,%6,%7}, {%8,%9}, {%0,%1,%2,%3};"
        : "+f"(c[0]), "+f"(c[1]), "+f"(c[2]), "+f"(c[3])
        : "r"(a[0]), "r"(a[1]), "r"(a[2]), "r"(a[3]), "r"(b[0]), "r"(b[1]));
}

// ---------------------------------------------------------------------------
// Fragment index helpers (uint32 units within one plane).
// A-frag of [M][K]: per m16-tile, per 16-k step: 32 lanes x 4 regs.
//   lane = (rr&7)*4 + (c&3); reg = (rr>>3) + (c>=4 ? 2 : 0)   (rr=m&15, c=kpair&7)
// B-frag of [N][K]: per n8-tile, per 16-k step: 32 lanes x 2 regs.
//   lane = (n&7)*4 + (c&3); reg = c>>2
// ---------------------------------------------------------------------------
__device__ __forceinline__ size_t idxA(int mtile, int KS, int ks, int rr, int c) {
    return ((((size_t)mtile * KS + ks) * 32) + (rr & 7) * 4 + (c & 3)) * 4 +
           (rr >> 3) + (((c & 7) >= 4) ? 2 : 0);
}
__device__ __forceinline__ size_t idxB(int ntile, int KS, int ks, int gb, int c) {
    return ((((size_t)ntile * KS + ks) * 32) + gb * 4 + (c & 3)) * 2 + ((c & 7) >> 2);
}

// ---------------------------------------------------------------------------
// Prepass: split fp32 matrix into fragment-layout hi/lo planes.
// ---------------------------------------------------------------------------
__global__ __launch_bounds__(256) void split_A_k(const float* __restrict__ X,
                                                 uint32_t* __restrict__ hi,
                                                 uint32_t* __restrict__ lo) {
    const int id = blockIdx.x * 256 + threadIdx.x;   // one k-pair each, K=1024
    const int m = id >> 9, kp = id & 511;
    const float2 x = *(const float2*)(X + (size_t)m * 1024 + kp * 2);
    uint32_t hp, lp;
    split2(x.x, x.y, hp, lp);
    const size_t idx = idxA(m >> 4, 64, kp >> 3, m & 15, kp & 7);
    hi[idx] = hp;
    lo[idx] = lp;
}
__global__ __launch_bounds__(256) void split_B_k(const float* __restrict__ W,
                                                 uint32_t* __restrict__ hi,
                                                 uint32_t* __restrict__ lo) {
    const int id = blockIdx.x * 256 + threadIdx.x;   // N=1024, K=1024
    const int n = id >> 9, kp = id & 511;
    const float2 x = *(const float2*)(W + (size_t)n * 1024 + kp * 2);
    uint32_t hp, lp;
    split2(x.x, x.y, hp, lp);
    const size_t idx = idxB(n >> 3, 64, kp >> 3, n & 7, kp & 7);
    hi[idx] = hp;
    lo[idx] = lp;
}

// ---------------------------------------------------------------------------
// Tensor-core GEMM on pre-split fragment operands, bf16x3, fp32 accum.
//   MODE 0: Q proj  -> qA frag (scale 1/8 folded)      [M=4096,N=1024,K=1024]
//   MODE 4: K proj  -> kB frag                          same shape
//   MODE 5: V proj  -> vB frag (transposed, STG.16)     same shape
//   MODE 1: scores  -> wts fp32   [per z: M=2048,N=2048,K=64]
//   MODE 3: PV      -> aA frag    [per z: M=2048,N=64,K=2048]; A = wts fp32,
//                       split in-kernel (each element read exactly once)
//   MODE 2: out proj-> out fp32 + bias  [M=4096,N=1024,K=1024]
// Block 128x(128|64), 8 warps (2m x 4n), warp tile 64x(32|16).
// ---------------------------------------------------------------------------
template <int MODE>
__global__ __launch_bounds__(256, 2) void gemm_k(
    const uint32_t* __restrict__ Ahi, const uint32_t* __restrict__ Alo,
    const uint32_t* __restrict__ Bhi, const uint32_t* __restrict__ Blo,
    const float* __restrict__ Af, const float* __restrict__ bias,
    float* __restrict__ Cf,
    uint32_t* __restrict__ Ohi, uint32_t* __restrict__ Olo) {
    constexpr int BM     = 128;
    constexpr int BN     = (MODE == 3) ? 64 : 128;
    constexpr int NT     = (MODE == 3) ? 2 : 4;          // n8-tiles per warp
    constexpr int NTILES = BN / 8;
    constexpr int KDIM   = (MODE == 1) ? 64 : ((MODE == 3) ? 2048 : 1024);
    constexpr int KS     = KDIM / 16;

    __shared__ __align__(16) uint32_t As[2][2][8][32][4];
    __shared__ __align__(16) uint32_t Bs[2][2][NTILES][32][2];

    const int tid  = threadIdx.x;
    const int lane = tid & 31;
    const int wid  = tid >> 5;
    const int wm   = wid >> 2;   // 0..1 -> m offset wm*64
    const int wn   = wid & 3;    // 0..3 -> n offset wn*(NT*8)
    const int g    = lane >> 2;
    const int t4   = lane & 3;
    const int m0   = blockIdx.y * BM;
    const int n0   = blockIdx.x * BN;
    const int z    = blockIdx.z;

    // Operand tile bases (fragment-tile units)
    int mtile0 = m0 >> 4;
    if constexpr (MODE == 1) mtile0 += z * 128;
    int ntile0 = n0 >> 3;
    if constexpr (MODE == 1) ntile0 += z * 256;
    if constexpr (MODE == 3) ntile0 = z * 8;

    float acc[4][NT][4];
#pragma unroll
    for (int i = 0; i < 4; ++i)
#pragma unroll
        for (int j = 0; j < NT; ++j)
#pragma unroll
            for (int r = 0; r < 4; ++r) acc[i][j][r] = 0.0f;

    uint4  ra[2], rbw[2];
    float4 raf[2];
    uint2  rb3[2];

    auto fetch = [&](int ks) {
        if constexpr (MODE == 3) {
#pragma unroll
            for (int it = 0; it < 2; ++it) {
                const int f4 = tid + it * 256;
                const int m  = f4 >> 2;
                const int kk = (f4 & 3) * 4;
                raf[it] = *(const float4*)(Af + ((size_t)z * S_ + m0 + m) * S_ + ks * 16 + kk);
            }
            const size_t b = (((size_t)ntile0 + (tid >> 5)) * KS + ks) * 64 + (lane) * 2;
            rb3[0] = *(const uint2*)(Bhi + b);
            rb3[1] = *(const uint2*)(Blo + b);
        } else {
            const size_t a = (((size_t)mtile0 + (tid >> 5)) * KS + ks) * 128 + lane * 4;
            ra[0] = *(const uint4*)(Ahi + a);
            ra[1] = *(const uint4*)(Alo + a);
            const size_t b = (((size_t)ntile0 + (tid >> 4)) * KS + ks) * 64 + (tid & 15) * 4;
            rbw[0] = *(const uint4*)(Bhi + b);
            rbw[1] = *(const uint4*)(Blo + b);
        }
    };

    auto stage = [&](int buf) {
        if constexpr (MODE == 3) {
            // A: split fp32 weights into fragment layout (scatter STS.32)
#pragma unroll
            for (int it = 0; it < 2; ++it) {
                const int f4    = tid + it * 256;
                const int m     = f4 >> 2;
                const int mtile = m >> 4;
                const int rr    = m & 15;
                const int gl    = rr & 7;
                const int rbase = rr >> 3;
                const int c0    = (f4 & 3) * 2;
                uint32_t hp, lp;
                split2(raf[it].x, raf[it].y, hp, lp);
                {
                    const int c = c0, t = c & 3, rs = rbase + ((c >= 4) ? 2 : 0);
                    As[buf][0][mtile][gl * 4 + t][rs] = hp;
                    As[buf][1][mtile][gl * 4 + t][rs] = lp;
                }
                split2(raf[it].z, raf[it].w, hp, lp);
                {
                    const int c = c0 + 1, t = c & 3, rs = rbase + ((c >= 4) ? 2 : 0);
                    As[buf][0][mtile][gl * 4 + t][rs] = hp;
                    As[buf][1][mtile][gl * 4 + t][rs] = lp;
                }
            }
            *(uint2*)&Bs[buf][0][tid >> 5][lane][0] = rb3[0];
            *(uint2*)&Bs[buf][1][tid >> 5][lane][0] = rb3[1];
        } else {
            *(uint4*)&As[buf][0][tid >> 5][lane][0] = ra[0];
            *(uint4*)&As[buf][1][tid >> 5][lane][0] = ra[1];
            *(uint4*)&Bs[buf][0][tid >> 4][(tid & 15) * 2][0] = rbw[0];
            *(uint4*)&Bs[buf][1][tid >> 4][(tid & 15) * 2][0] = rbw[1];
        }
    };

    auto compute = [&](int buf) {
        uint32_t bh[NT][2], bl[NT][2];
#pragma unroll
        for (int nt = 0; nt < NT; ++nt) {
            *(uint2*)bh[nt] = *(const uint2*)&Bs[buf][0][wn * NT + nt][lane][0];
            *(uint2*)bl[nt] = *(const uint2*)&Bs[buf][1][wn * NT + nt][lane][0];
        }
#pragma unroll
        for (int mt = 0; mt < 4; ++mt) {
            uint32_t ah[4], al[4];
            *(uint4*)ah = *(const uint4*)&As[buf][0][wm * 4 + mt][lane][0];
            *(uint4*)al = *(const uint4*)&As[buf][1][wm * 4 + mt][lane][0];
#pragma unroll
            for (int nt = 0; nt < NT; ++nt) {
                mma16816(acc[mt][nt], ah, bh[nt]);
                mma16816(acc[mt][nt], ah, bl[nt]);
                mma16816(acc[mt][nt], al, bh[nt]);
            }
        }
    };

    fetch(0);
    stage(0);
    __syncthreads();
#pragma unroll 1
    for (int t = 0; t < KS; ++t) {
        if (t + 1 < KS) fetch(t + 1);
        compute(t & 1);
        if (t + 1 < KS) stage((t + 1) & 1);
        __syncthreads();
    }

    // ---- Epilogue ----
#pragma unroll
    for (int mt = 0; mt < 4; ++mt) {
#pragma unroll
        for (int nt = 0; nt < NT; ++nt) {
            const int col = n0 + wn * (NT * 8) + nt * 8 + t4 * 2;
            float b0 = 0.0f, b1 = 0.0f;
            if constexpr (MODE == 0 || MODE == 4 || MODE == 5 || MODE == 2) {
                b0 = bias[col];
                b1 = bias[col + 1];
            }
#pragma unroll
            for (int rs = 0; rs < 2; ++rs) {
                const int row = m0 + wm * 64 + mt * 16 + g + rs * 8;
                const float v0 = acc[mt][nt][rs * 2 + 0];
                const float v1 = acc[mt][nt][rs * 2 + 1];
                if constexpr (MODE == 0) {          // Q proj -> qA frag
                    const int b = row >> 11, s = row & 2047;
                    const int h = col >> 6, d = col & 63;
                    const int z2 = b * H_ + h;
                    uint32_t hp, lp;
                    split2((v0 + b0) * 0.125f, (v1 + b1) * 0.125f, hp, lp);
                    const size_t idx = idxA(z2 * 128 + (s >> 4), 4, d >> 4, s & 15, (d & 15) >> 1);
                    Ohi[idx] = hp;
                    Olo[idx] = lp;
                } else if constexpr (MODE == 4) {   // K proj -> kB frag
                    const int b = row >> 11, s = row & 2047;
                    const int h = col >> 6, d = col & 63;
                    const int z2 = b * H_ + h;
                    uint32_t hp, lp;
                    split2(v0 + b0, v1 + b1, hp, lp);
                    const size_t idx = idxB(z2 * 256 + (s >> 3), 4, d >> 4, s & 7, (d & 15) >> 1);
                    Ohi[idx] = hp;
                    Olo[idx] = lp;
                } else if constexpr (MODE == 5) {   // V proj -> vB frag (k = s)
                    const int b = row >> 11, s = row & 2047;
                    const int h = col >> 6, d = col & 63;
                    const int z2 = b * H_ + h;
                    const int c = (s & 15) >> 1;
#pragma unroll
                    for (int j = 0; j < 2; ++j) {
                        const int dd = d + j;
                        uint16_t hh, ll;
                        split1((j ? v1 + b1 : v0 + b0), hh, ll);
                        const size_t idx = idxB(z2 * 8 + (dd >> 3), 128, s >> 4, dd & 7, c);
                        ((uint16_t*)&Ohi[idx])[s & 1] = hh;
                        ((uint16_t*)&Olo[idx])[s & 1] = ll;
                    }
                } else if constexpr (MODE == 1) {   // scores -> fp32 logits
                    *(float2*)(Cf + ((size_t)z * S_ + row) * S_ + col) = make_float2(v0, v1);
                } else if constexpr (MODE == 3) {   // PV -> aA frag
                    const int bb = z >> 4, h = z & 15;
                    const int m = bb * 2048 + row;
                    const int kk = h * 64 + col;
                    uint32_t hp, lp;
                    split2(v0, v1, hp, lp);
                    const size_t idx = idxA(m >> 4, 64, kk >> 4, m & 15, (kk & 15) >> 1);
                    Ohi[idx] = hp;
                    Olo[idx] = lp;
                } else {                            // MODE 2: out proj
                    *(float2*)(Cf + (size_t)row * D_ + col) = make_float2(v0 + b0, v1 + b1);
                }
            }
        }
    }
}

// ---------------------------------------------------------------------------
// In-place row softmax on [rows, 2048], one block/row, register-resident.
// ---------------------------------------------------------------------------
__global__ __launch_bounds__(256) void softmax_k(float* __restrict__ W) {
    const size_t row = blockIdx.x;
    float* p = W + row * (size_t)S_;
    const int tid = threadIdx.x;
    const int wr  = tid >> 5;
    const int ln  = tid & 31;

    const float4 v0 = *(const float4*)(p + tid * 8);
    const float4 v1 = *(const float4*)(p + tid * 8 + 4);
    float x[8] = {v0.x, v0.y, v0.z, v0.w, v1.x, v1.y, v1.z, v1.w};

    float mx = x[0];
#pragma unroll
    for (int i = 1; i < 8; ++i) mx = fmaxf(mx, x[i]);
#pragma unroll
    for (int o = 16; o > 0; o >>= 1) mx = fmaxf(mx, __shfl_xor_sync(0xFFFFFFFFu, mx, o));

    __shared__ float red_mx[8];
    __shared__ float red_sm[8];
    if (ln == 0) red_mx[wr] = mx;
    __syncthreads();
    mx = red_mx[0];
#pragma unroll
    for (int i = 1; i < 8; ++i) mx = fmaxf(mx, red_mx[i]);

    float e[8];
    float s = 0.0f;
#pragma unroll
    for (int i = 0; i < 8; ++i) {
        e[i] = expf(x[i] - mx);
        s += e[i];
    }
#pragma unroll
    for (int o = 16; o > 0; o >>= 1) s += __shfl_xor_sync(0xFFFFFFFFu, s, o);
    if (ln == 0) red_sm[wr] = s;
    __syncthreads();
    s = red_sm[0];
#pragma unroll
    for (int i = 1; i < 8; ++i) s += red_sm[i];
    const float inv = 1.0f / s;

    float4 o0 = {e[0] * inv, e[1] * inv, e[2] * inv, e[3] * inv};
    float4 o1 = {e[4] * inv, e[5] * inv, e[6] * inv, e[7] * inv};
    *(float4*)(p + tid * 8)     = o0;
    *(float4*)(p + tid * 8 + 4) = o1;
}

// ---------------------------------------------------------------------------
// Launch. Inputs: q,k,v,mask,Wq,bq,Wk,bk,Wv,bv,Wo,bo.
// Output: out [B,S,D] then weights [B,H,S,S]. mask*1e-9 is below fp32 ulp of
// O(1) logits -> skipped.
// ---------------------------------------------------------------------------
extern "C" void kernel_launch(void* const* d_in, const int* in_sizes, int n_in,
                              void* d_out, int out_size) {
    (void)in_sizes; (void)n_in; (void)out_size;

    const float* q  = (const float*)d_in[0];
    const float* k  = (const float*)d_in[1];
    const float* v  = (const float*)d_in[2];
    const float* Wq = (const float*)d_in[4];
    const float* bq = (const float*)d_in[5];
    const float* Wk = (const float*)d_in[6];
    const float* bk = (const float*)d_in[7];
    const float* Wv = (const float*)d_in[8];
    const float* bv = (const float*)d_in[9];
    const float* Wo = (const float*)d_in[10];
    const float* bo = (const float*)d_in[11];

    float* out = (float*)d_out;
    float* wts = out + (size_t)B_ * S_ * D_;   // weights region (logits scratch)

    uint32_t *xA, *WB, *qA, *kB, *vB, *aA;
    cudaGetSymbolAddress((void**)&xA, g_xA);
    cudaGetSymbolAddress((void**)&WB, g_WB);
    cudaGetSymbolAddress((void**)&qA, g_qA);
    cudaGetSymbolAddress((void**)&kB, g_kB);
    cudaGetSymbolAddress((void**)&vB, g_vB);
    cudaGetSymbolAddress((void**)&aA, g_aA);

    const dim3 blk(256);

    // Prepass: split inputs + weights into fragment layout
    split_A_k<<<8192, blk>>>(q, xA + 0 * 2 * PLANE, xA + (0 * 2 + 1) * PLANE);
    split_A_k<<<8192, blk>>>(k, xA + 1 * 2 * PLANE, xA + (1 * 2 + 1) * PLANE);
    split_A_k<<<8192, blk>>>(v, xA + 2 * 2 * PLANE, xA + (2 * 2 + 1) * PLANE);
    split_B_k<<<2048, blk>>>(Wq, WB + 0 * 2 * WPL, WB + (0 * 2 + 1) * WPL);
    split_B_k<<<2048, blk>>>(Wk, WB + 1 * 2 * WPL, WB + (1 * 2 + 1) * WPL);
    split_B_k<<<2048, blk>>>(Wv, WB + 2 * 2 * WPL, WB + (2 * 2 + 1) * WPL);
    split_B_k<<<2048, blk>>>(Wo, WB + 3 * 2 * WPL, WB + (3 * 2 + 1) * WPL);

    // Projections (fragment-layout outputs; 1/sqrt(depth) folded into Q)
    const dim3 gproj(D_ / 128, (B_ * S_) / 128, 1);
    gemm_k<0><<<gproj, blk>>>(xA + 0 * 2 * PLANE, xA + (0 * 2 + 1) * PLANE,
                              WB + 0 * 2 * WPL, WB + (0 * 2 + 1) * WPL,
                              nullptr, bq, nullptr, qA, qA + PLANE);
    gemm_k<4><<<gproj, blk>>>(xA + 1 * 2 * PLANE, xA + (1 * 2 + 1) * PLANE,
                              WB + 1 * 2 * WPL, WB + (1 * 2 + 1) * WPL,
                              nullptr, bk, nullptr, kB, kB + PLANE);
    gemm_k<5><<<gproj, blk>>>(xA + 2 * 2 * PLANE, xA + (2 * 2 + 1) * PLANE,
                              WB + 2 * 2 * WPL, WB + (2 * 2 + 1) * WPL,
                              nullptr, bv, nullptr, vB, vB + PLANE);

    // Scores -> d_out weights region
    const dim3 gsc(S_ / 128, S_ / 128, B_ * H_);
    gemm_k<1><<<gsc, blk>>>(qA, qA + PLANE, kB, kB + PLANE,
                            nullptr, nullptr, wts, nullptr, nullptr);

    // In-place softmax
    softmax_k<<<B_ * H_ * S_, blk>>>(wts);

    // PV: attn = weights @ V -> aA frag
    const dim3 gpv(1, S_ / 128, B_ * H_);
    gemm_k<3><<<gpv, blk>>>(nullptr, nullptr, vB, vB + PLANE,
                            wts, nullptr, nullptr, aA, aA + PLANE);

    // Output projection
    const dim3 gout(D_ / 128, (B_ * S_) / 128, 1);
    gemm_k<2><<<gout, blk>>>(aA, aA + PLANE, WB + 3 * 2 * WPL, WB + (3 * 2 + 1) * WPL,
                             nullptr, bo, out, nullptr, nullptr);
}